// round 1
// baseline (speedup 1.0000x reference)
#include <cuda_runtime.h>
#include <cuda_bf16.h>
#include <math.h>

// ============================================================================
// VNETDetector: NN+softmax per step (parallel), Viterbi ACS scan (sequential,
// single thread with packed f32x2 add + FMNMX), bit extraction from checkpoints
// (parallel replay, bit-exact).
// ============================================================================

#define T_CAP      250112               // multiple of 128 and 16, >= 250000
#define SEG_STEPS  128
#define NSEG       4                    // ring: 4 * 128 * 64B = 32 KB
#define CKPT_STRIDE 16

// llr rows stored interleaved per t (16 floats = 4 float4):
//   q0 = (l0,l1,l8,l9)  q1 = (l2,l3,l10,l11)  q2 = (l4,l5,l12,l13)  q3 = (l6,l7,l14,l15)
__device__ __align__(16) float4 g_llr4[T_CAP * 4];          // 16 MB
__device__ __align__(16) float4 g_ckpt[(T_CAP / CKPT_STRIDE) * 2];  // 8 floats per chunk

// ---------------- f32x2 helpers (round identically to scalar FADD.RN) -------
__device__ __forceinline__ unsigned long long f2_pack(float a, float b) {
    unsigned long long r;
    asm("mov.b64 %0, {%1, %2};" : "=l"(r) : "f"(a), "f"(b));
    return r;
}
__device__ __forceinline__ void f2_unpack(unsigned long long v, float& a, float& b) {
    asm("mov.b64 {%0, %1}, %2;" : "=f"(a), "=f"(b) : "l"(v));
}
__device__ __forceinline__ unsigned long long f2_add(unsigned long long a, unsigned long long b) {
    unsigned long long r;
    asm("add.rn.f32x2 %0, %1, %2;" : "=l"(r) : "l"(a), "l"(b));
    return r;
}

// ============================================================================
// K1: per-t NN forward, log_softmax -> llrs (interleaved), argmax bit + max prob
// ============================================================================
__global__ __launch_bounds__(128)
void k1_llr(const float* __restrict__ rx,
            const float* __restrict__ W1, const float* __restrict__ b1,
            const float* __restrict__ W2, const float* __restrict__ b2,
            float* __restrict__ out_cbits, float* __restrict__ out_conf, int T)
{
    __shared__ float sW1[100], sb1[100], sW2[1600], sb2[16];
    for (int k = threadIdx.x; k < 100;  k += blockDim.x) { sW1[k] = W1[k]; sb1[k] = b1[k]; }
    for (int k = threadIdx.x; k < 1600; k += blockDim.x) { sW2[k] = W2[k]; }
    for (int k = threadIdx.x; k < 16;   k += blockDim.x) { sb2[k] = b2[k]; }
    __syncthreads();

    int t = blockIdx.x * blockDim.x + threadIdx.x;
    if (t >= T) return;

    float x = rx[t];

    float acc[16];
#pragma unroll
    for (int i = 0; i < 16; i++) acc[i] = 0.0f;

    // h = relu(x*W1[j] + b1[j]); logits[i] += h * W2[i][j]  (j ascending, like a
    // sequential dot)
#pragma unroll 4
    for (int j = 0; j < 100; j++) {
        float h = fmaxf(__fadd_rn(__fmul_rn(x, sW1[j]), sb1[j]), 0.0f);
#pragma unroll
        for (int i = 0; i < 16; i++)
            acc[i] = __fmaf_rn(h, sW2[i * 100 + j], acc[i]);
    }
#pragma unroll
    for (int i = 0; i < 16; i++) acc[i] = __fadd_rn(acc[i], sb2[i]);

    // log_softmax (stable, matching jax.nn.log_softmax structure)
    float m = acc[0];
#pragma unroll
    for (int i = 1; i < 16; i++) m = fmaxf(m, acc[i]);

    float sh[16];
    float S = 0.0f;
#pragma unroll
    for (int i = 0; i < 16; i++) {
        sh[i] = __fadd_rn(acc[i], -m);
        S = __fadd_rn(S, expf(sh[i]));
    }
    float lse = logf(S);

    float llr[16];
    float best = -1.0f;
    int bi = 0;
#pragma unroll
    for (int i = 0; i < 16; i++) {
        float lp = __fadd_rn(sh[i], -lse);
        llr[i] = -lp;
        float p = expf(lp);
        if (p > best) { best = p; bi = i; }   // strict > keeps first occurrence
    }

    out_cbits[t] = (float)(bi & 1);
    out_conf[t]  = best;

    float4* dst = g_llr4 + (size_t)t * 4;
    dst[0] = make_float4(llr[0], llr[1], llr[8],  llr[9]);
    dst[1] = make_float4(llr[2], llr[3], llr[10], llr[11]);
    dst[2] = make_float4(llr[4], llr[5], llr[12], llr[13]);
    dst[3] = make_float4(llr[6], llr[7], llr[14], llr[15]);
}

// ============================================================================
// K2: sequential ACS scan. 1 block, 128 threads.
//   warp 0 / lane 0 : consumer (the scan chain, packed f32x2)
//   warps 1..3      : producers filling the shared llr ring (SMSPs 1..3)
// 8-state reduction: v[i] == v[i+8] exactly, so state = w[0..7].
//   w'[i] = min(w[(2i)&7] + l[2i], w[(2i+1)&7] + l[2i+1]), i = 0..7
// Checkpoints (w before step t, t % 16 == 0) written to g_ckpt for K3 replay.
// ============================================================================
__global__ __launch_bounds__(128, 1)
void k2_scan(int T)
{
    __shared__ float4 ring[NSEG * SEG_STEPS * 4];   // 32 KB
    __shared__ volatile int s_ready[NSEG];
    __shared__ volatile int s_freed[NSEG];

    int tid  = threadIdx.x;
    int wid  = tid >> 5;
    int lane = tid & 31;

    if (tid < NSEG) { s_ready[tid] = 0; s_freed[tid] = 0; }
    __syncthreads();

    int nSegs = (T + SEG_STEPS - 1) / SEG_STEPS;

    if (wid >= 1) {
        // ------------------ producers ------------------
        for (int s = wid - 1; s < nSegs; s += 3) {
            int slot = s & (NSEG - 1);
            if (lane == 0) {
                while (s_freed[slot] < s + 1 - NSEG) __nanosleep(64);
            }
            __syncwarp();
            const float4* src = g_llr4 + (size_t)s * SEG_STEPS * 4;
            float4* dst = ring + slot * SEG_STEPS * 4;
#pragma unroll
            for (int k = 0; k < (SEG_STEPS * 4) / 32; k++)
                dst[k * 32 + lane] = src[k * 32 + lane];
            __syncwarp();
            __threadfence_block();
            if (lane == 0) s_ready[slot] = s + 1;
        }
    } else if (tid == 0) {
        // ------------------ consumer (the chain) ------------------
        unsigned long long P01 = 0ull, P23 = 0ull, P45 = 0ull, P67 = 0ull; // (0.f,0.f) pairs
        int t = 0;

        for (int s = 0; s < nSegs; s++) {
            int slot = s & (NSEG - 1);
            while (s_ready[slot] < s + 1) { /* spin */ }
            __threadfence_block();

            const float4* base = ring + slot * SEG_STEPS * 4;
            int steps = min(SEG_STEPS, T - s * SEG_STEPS);

            int nblk = steps >> 4;          // full 16-step blocks
            for (int blk = 0; blk < nblk; blk++) {
                // checkpoint w before step t (t multiple of 16)
                {
                    float w0, w1, w2, w3, w4, w5, w6, w7;
                    f2_unpack(P01, w0, w1); f2_unpack(P23, w2, w3);
                    f2_unpack(P45, w4, w5); f2_unpack(P67, w6, w7);
                    float4* ck = g_ckpt + (size_t)(t >> 4) * 2;
                    ck[0] = make_float4(w0, w1, w2, w3);
                    ck[1] = make_float4(w4, w5, w6, w7);
                }
                const float4* bb = base + blk * 16 * 4;
#pragma unroll
                for (int j = 0; j < 16; j++) {
                    float4 q0 = bb[j * 4 + 0];
                    float4 q1 = bb[j * 4 + 1];
                    float4 q2 = bb[j * 4 + 2];
                    float4 q3 = bb[j * 4 + 3];
                    unsigned long long a = f2_add(P01, f2_pack(q0.x, q0.y)); // (w0+l0 , w1+l1 )
                    unsigned long long b = f2_add(P01, f2_pack(q0.z, q0.w)); // (w0+l8 , w1+l9 )
                    unsigned long long c = f2_add(P23, f2_pack(q1.x, q1.y));
                    unsigned long long d = f2_add(P23, f2_pack(q1.z, q1.w));
                    unsigned long long e = f2_add(P45, f2_pack(q2.x, q2.y));
                    unsigned long long f = f2_add(P45, f2_pack(q2.z, q2.w));
                    unsigned long long g = f2_add(P67, f2_pack(q3.x, q3.y));
                    unsigned long long h = f2_add(P67, f2_pack(q3.z, q3.w));
                    float alo, ahi, blo, bhi, clo, chi, dlo, dhi;
                    float elo, ehi, flo, fhi, glo, ghi, hlo, hhi;
                    f2_unpack(a, alo, ahi); f2_unpack(b, blo, bhi);
                    f2_unpack(c, clo, chi); f2_unpack(d, dlo, dhi);
                    f2_unpack(e, elo, ehi); f2_unpack(f, flo, fhi);
                    f2_unpack(g, glo, ghi); f2_unpack(h, hlo, hhi);
                    float nw0 = fminf(alo, ahi);   // w'0
                    float nw4 = fminf(blo, bhi);   // w'4
                    float nw1 = fminf(clo, chi);   // w'1
                    float nw5 = fminf(dlo, dhi);   // w'5
                    float nw2 = fminf(elo, ehi);   // w'2
                    float nw6 = fminf(flo, fhi);   // w'6
                    float nw3 = fminf(glo, ghi);   // w'3
                    float nw7 = fminf(hlo, hhi);   // w'7
                    P01 = f2_pack(nw0, nw1);
                    P23 = f2_pack(nw2, nw3);
                    P45 = f2_pack(nw4, nw5);
                    P67 = f2_pack(nw6, nw7);
                }
                t += 16;
            }
            // tail (< 16 steps) — T=250000 is a multiple of 16 so this stores a
            // checkpoint at the block start then finishes remaining steps.
            int rem = steps - (nblk << 4);
            if (rem > 0) {
                if ((t & 15) == 0) {
                    float w0, w1, w2, w3, w4, w5, w6, w7;
                    f2_unpack(P01, w0, w1); f2_unpack(P23, w2, w3);
                    f2_unpack(P45, w4, w5); f2_unpack(P67, w6, w7);
                    float4* ck = g_ckpt + (size_t)(t >> 4) * 2;
                    ck[0] = make_float4(w0, w1, w2, w3);
                    ck[1] = make_float4(w4, w5, w6, w7);
                }
                const float4* bb = base + (nblk << 4) * 4;
                for (int j = 0; j < rem; j++) {
                    float4 q0 = bb[j * 4 + 0], q1 = bb[j * 4 + 1];
                    float4 q2 = bb[j * 4 + 2], q3 = bb[j * 4 + 3];
                    unsigned long long a = f2_add(P01, f2_pack(q0.x, q0.y));
                    unsigned long long b = f2_add(P01, f2_pack(q0.z, q0.w));
                    unsigned long long c = f2_add(P23, f2_pack(q1.x, q1.y));
                    unsigned long long d = f2_add(P23, f2_pack(q1.z, q1.w));
                    unsigned long long e = f2_add(P45, f2_pack(q2.x, q2.y));
                    unsigned long long f = f2_add(P45, f2_pack(q2.z, q2.w));
                    unsigned long long g = f2_add(P67, f2_pack(q3.x, q3.y));
                    unsigned long long h = f2_add(P67, f2_pack(q3.z, q3.w));
                    float alo, ahi, blo, bhi, clo, chi, dlo, dhi;
                    float elo, ehi, flo, fhi, glo, ghi, hlo, hhi;
                    f2_unpack(a, alo, ahi); f2_unpack(b, blo, bhi);
                    f2_unpack(c, clo, chi); f2_unpack(d, dlo, dhi);
                    f2_unpack(e, elo, ehi); f2_unpack(f, flo, fhi);
                    f2_unpack(g, glo, ghi); f2_unpack(h, hlo, hhi);
                    P01 = f2_pack(fminf(alo, ahi), fminf(clo, chi));
                    P23 = f2_pack(fminf(elo, ehi), fminf(glo, ghi));
                    P45 = f2_pack(fminf(blo, bhi), fminf(dlo, dhi));
                    P67 = f2_pack(fminf(flo, fhi), fminf(hlo, hhi));
                }
                t += rem;
            }
            __threadfence_block();
            s_freed[slot] = s + 1;
        }
    }
}

// ============================================================================
// K3: replay each 16-step chunk from its checkpoint, emit detected bits.
// Bit-exact: same __fadd_rn / fminf ops, same order, same llr inputs.
// bit[t] = argmin(v_t) % 2 ; v has 8 distinct states, first occurrence in 0..7.
// ============================================================================
__global__ __launch_bounds__(128)
void k3_bits(float* __restrict__ out_bits, int T)
{
    int c = blockIdx.x * blockDim.x + threadIdx.x;
    int t0 = c * CKPT_STRIDE;
    if (t0 >= T) return;

    float4 c0 = g_ckpt[(size_t)c * 2 + 0];
    float4 c1 = g_ckpt[(size_t)c * 2 + 1];
    float w0 = c0.x, w1 = c0.y, w2 = c0.z, w3 = c0.w;
    float w4 = c1.x, w5 = c1.y, w6 = c1.z, w7 = c1.w;

    int n = min(CKPT_STRIDE, T - t0);
    for (int j = 0; j < n; j++) {
        // argmin, first occurrence (strict <)
        float best = w0; int bi = 0;
        if (w1 < best) { best = w1; bi = 1; }
        if (w2 < best) { best = w2; bi = 2; }
        if (w3 < best) { best = w3; bi = 3; }
        if (w4 < best) { best = w4; bi = 4; }
        if (w5 < best) { best = w5; bi = 5; }
        if (w6 < best) { best = w6; bi = 6; }
        if (w7 < best) { best = w7; bi = 7; }
        out_bits[t0 + j] = (float)(bi & 1);

        const float4* q = g_llr4 + (size_t)(t0 + j) * 4;
        float4 q0 = q[0], q1 = q[1], q2 = q[2], q3 = q[3];
        float nw0 = fminf(__fadd_rn(w0, q0.x), __fadd_rn(w1, q0.y));
        float nw4 = fminf(__fadd_rn(w0, q0.z), __fadd_rn(w1, q0.w));
        float nw1 = fminf(__fadd_rn(w2, q1.x), __fadd_rn(w3, q1.y));
        float nw5 = fminf(__fadd_rn(w2, q1.z), __fadd_rn(w3, q1.w));
        float nw2 = fminf(__fadd_rn(w4, q2.x), __fadd_rn(w5, q2.y));
        float nw6 = fminf(__fadd_rn(w4, q2.z), __fadd_rn(w5, q2.w));
        float nw3 = fminf(__fadd_rn(w6, q3.x), __fadd_rn(w7, q3.y));
        float nw7 = fminf(__fadd_rn(w6, q3.z), __fadd_rn(w7, q3.w));
        w0 = nw0; w1 = nw1; w2 = nw2; w3 = nw3;
        w4 = nw4; w5 = nw5; w6 = nw6; w7 = nw7;
    }
}

// ============================================================================
extern "C" void kernel_launch(void* const* d_in, const int* in_sizes, int n_in,
                              void* d_out, int out_size)
{
    const float* rx = (const float*)d_in[0];
    const float* W1 = (const float*)d_in[1];
    const float* b1 = (const float*)d_in[2];
    const float* W2 = (const float*)d_in[3];
    const float* b2 = (const float*)d_in[4];
    int T = in_sizes[0];

    float* out = (float*)d_out;
    // Output layout: [detected_word (T)] [confident_bits (T)] [confidence_word (T)]
    int sections = (T > 0) ? (out_size / T) : 0;
    float* out_det = out;
    float* out_cb  = (sections >= 2) ? out + T     : out;        // fallback: overwrite-safe
    float* out_cw  = (sections >= 3) ? out + 2 * T : out_cb;

    // K1: llrs + confidence outputs (parallel)
    int grid1 = (T + 127) / 128;
    k1_llr<<<grid1, 128>>>(rx, W1, b1, W2, b2, out_cb, out_cw, T);

    // K2: sequential scan (1 block: 1 consumer lane + 3 producer warps)
    k2_scan<<<1, 128>>>(T);

    // K3: bit extraction from checkpoints (parallel)
    int nChunks = (T + CKPT_STRIDE - 1) / CKPT_STRIDE;
    int grid3 = (nChunks + 127) / 128;
    k3_bits<<<grid3, 128>>>(out_det, T);

    // K1 runs after nothing, K2 after K1, K3 after K2 — same stream ordering.
}

// round 2
// speedup vs baseline: 1.6314x; 1.6314x over previous
#include <cuda_runtime.h>
#include <cuda_bf16.h>
#include <math.h>

// ============================================================================
// VNETDetector: NN+softmax per step (parallel), Viterbi ACS scan (sequential,
// single thread, one fused PTX block per step: 8x add.rn.f32x2 + 8x min.f32),
// bit extraction from checkpoints (parallel replay, bit-exact).
// ============================================================================

#define T_CAP      250112               // multiple of 128 and 16, >= 250000
#define SEG_STEPS  128
#define NSEG       4                    // ring: 4 * 128 * 64B = 32 KB
#define CKPT_STRIDE 16

// llr rows stored interleaved per t (16 floats = 4 float4 = 8 packed pairs):
//   q0 = (l0,l1),(l8,l9)  q1 = (l2,l3),(l10,l11)
//   q2 = (l4,l5),(l12,l13) q3 = (l6,l7),(l14,l15)
__device__ __align__(16) float4 g_llr4[T_CAP * 4];          // 16 MB
__device__ __align__(16) float4 g_ckpt[(T_CAP / CKPT_STRIDE) * 2];  // 8 floats/chunk

// ---------------- helpers ---------------------------------------------------
__device__ __forceinline__ void f2_unpack(unsigned long long v, float& a, float& b) {
    asm("mov.b64 {%0, %1}, %2;" : "=f"(a), "=f"(b) : "l"(v));
}

// One ACS step, fully fused. States as 4 packed pairs:
//   P01=(w0,w1) P23=(w2,w3) P45=(w4,w5) P67=(w6,w7)
// LLR pairs: La=(l0,l1) Lb=(l8,l9) Lc=(l2,l3) Ld=(l10,l11)
//            Le=(l4,l5) Lf=(l12,l13) Lg=(l6,l7) Lh=(l14,l15)
// add.rn.f32x2 is lanewise FADD.RN (bit-exact vs scalar); min.f32 == fminf.
__device__ __forceinline__ void acs_step(
    unsigned long long& P01, unsigned long long& P23,
    unsigned long long& P45, unsigned long long& P67,
    unsigned long long La, unsigned long long Lb,
    unsigned long long Lc, unsigned long long Ld,
    unsigned long long Le, unsigned long long Lf,
    unsigned long long Lg, unsigned long long Lh)
{
    asm("{\n\t"
        ".reg .f32 a0,a1,b0,b1,c0,c1,d0,d1,e0,e1,f0,f1,g0,g1,h0,h1;\n\t"
        ".reg .b64 ta,tb,tc,td,te,tf,tg,th;\n\t"
        "add.rn.f32x2 ta, %0, %4;\n\t"   // (w0+l0 , w1+l1 ) -> nw0
        "add.rn.f32x2 tb, %0, %5;\n\t"   // (w0+l8 , w1+l9 ) -> nw4
        "add.rn.f32x2 tc, %1, %6;\n\t"   // (w2+l2 , w3+l3 ) -> nw1
        "add.rn.f32x2 td, %1, %7;\n\t"   // (w2+l10, w3+l11) -> nw5
        "add.rn.f32x2 te, %2, %8;\n\t"   // (w4+l4 , w5+l5 ) -> nw2
        "add.rn.f32x2 tf, %2, %9;\n\t"   // (w4+l12, w5+l13) -> nw6
        "add.rn.f32x2 tg, %3, %10;\n\t"  // (w6+l6 , w7+l7 ) -> nw3
        "add.rn.f32x2 th, %3, %11;\n\t"  // (w6+l14, w7+l15) -> nw7
        "mov.b64 {a0,a1}, ta;\n\t"
        "mov.b64 {b0,b1}, tb;\n\t"
        "mov.b64 {c0,c1}, tc;\n\t"
        "mov.b64 {d0,d1}, td;\n\t"
        "mov.b64 {e0,e1}, te;\n\t"
        "mov.b64 {f0,f1}, tf;\n\t"
        "mov.b64 {g0,g1}, tg;\n\t"
        "mov.b64 {h0,h1}, th;\n\t"
        "min.f32 a0, a0, a1;\n\t"        // nw0
        "min.f32 b0, b0, b1;\n\t"        // nw4
        "min.f32 c0, c0, c1;\n\t"        // nw1
        "min.f32 d0, d0, d1;\n\t"        // nw5
        "min.f32 e0, e0, e1;\n\t"        // nw2
        "min.f32 f0, f0, f1;\n\t"        // nw6
        "min.f32 g0, g0, g1;\n\t"        // nw3
        "min.f32 h0, h0, h1;\n\t"        // nw7
        "mov.b64 %0, {a0, c0};\n\t"      // P01' = (nw0,nw1)
        "mov.b64 %1, {e0, g0};\n\t"      // P23' = (nw2,nw3)
        "mov.b64 %2, {b0, d0};\n\t"      // P45' = (nw4,nw5)
        "mov.b64 %3, {f0, h0};\n\t"      // P67' = (nw6,nw7)
        "}"
        : "+l"(P01), "+l"(P23), "+l"(P45), "+l"(P67)
        : "l"(La), "l"(Lb), "l"(Lc), "l"(Ld),
          "l"(Le), "l"(Lf), "l"(Lg), "l"(Lh));
}

// ============================================================================
// K1: per-t NN forward, log_softmax -> llrs (interleaved), argmax bit + max prob
// ============================================================================
__global__ __launch_bounds__(128)
void k1_llr(const float* __restrict__ rx,
            const float* __restrict__ W1, const float* __restrict__ b1,
            const float* __restrict__ W2, const float* __restrict__ b2,
            float* __restrict__ out_cbits, float* __restrict__ out_conf, int T)
{
    __shared__ float sW1[100], sb1[100], sW2[1600], sb2[16];
    for (int k = threadIdx.x; k < 100;  k += blockDim.x) { sW1[k] = W1[k]; sb1[k] = b1[k]; }
    for (int k = threadIdx.x; k < 1600; k += blockDim.x) { sW2[k] = W2[k]; }
    for (int k = threadIdx.x; k < 16;   k += blockDim.x) { sb2[k] = b2[k]; }
    __syncthreads();

    int t = blockIdx.x * blockDim.x + threadIdx.x;
    if (t >= T) return;

    float x = rx[t];

    float acc[16];
#pragma unroll
    for (int i = 0; i < 16; i++) acc[i] = 0.0f;

#pragma unroll 4
    for (int j = 0; j < 100; j++) {
        float h = fmaxf(__fadd_rn(__fmul_rn(x, sW1[j]), sb1[j]), 0.0f);
#pragma unroll
        for (int i = 0; i < 16; i++)
            acc[i] = __fmaf_rn(h, sW2[i * 100 + j], acc[i]);
    }
#pragma unroll
    for (int i = 0; i < 16; i++) acc[i] = __fadd_rn(acc[i], sb2[i]);

    float m = acc[0];
#pragma unroll
    for (int i = 1; i < 16; i++) m = fmaxf(m, acc[i]);

    float sh[16];
    float S = 0.0f;
#pragma unroll
    for (int i = 0; i < 16; i++) {
        sh[i] = __fadd_rn(acc[i], -m);
        S = __fadd_rn(S, expf(sh[i]));
    }
    float lse = logf(S);

    float llr[16];
    float best = -1.0f;
    int bi = 0;
#pragma unroll
    for (int i = 0; i < 16; i++) {
        float lp = __fadd_rn(sh[i], -lse);
        llr[i] = -lp;
        float p = expf(lp);
        if (p > best) { best = p; bi = i; }   // strict > keeps first occurrence
    }

    out_cbits[t] = (float)(bi & 1);
    out_conf[t]  = best;

    float4* dst = g_llr4 + (size_t)t * 4;
    dst[0] = make_float4(llr[0], llr[1], llr[8],  llr[9]);
    dst[1] = make_float4(llr[2], llr[3], llr[10], llr[11]);
    dst[2] = make_float4(llr[4], llr[5], llr[12], llr[13]);
    dst[3] = make_float4(llr[6], llr[7], llr[14], llr[15]);
}

// ============================================================================
// K2: sequential ACS scan. 1 block, 128 threads.
//   warp 0 / lane 0 : consumer chain (SMSP 0, no issue contention)
//   warps 1..3      : producers filling the shared llr ring (SMSPs 1..3)
// ============================================================================
__global__ __launch_bounds__(128, 1)
void k2_scan(int T)
{
    __shared__ __align__(16) float4 ring[NSEG * SEG_STEPS * 4];   // 32 KB
    __shared__ volatile int s_ready[NSEG];
    __shared__ volatile int s_freed[NSEG];

    int tid  = threadIdx.x;
    int wid  = tid >> 5;
    int lane = tid & 31;

    if (tid < NSEG) { s_ready[tid] = 0; s_freed[tid] = 0; }
    __syncthreads();

    int nSegs = (T + SEG_STEPS - 1) / SEG_STEPS;

    if (wid >= 1) {
        // ------------------ producers ------------------
        for (int s = wid - 1; s < nSegs; s += 3) {
            int slot = s & (NSEG - 1);
            if (lane == 0) {
                while (s_freed[slot] < s + 1 - NSEG) __nanosleep(64);
            }
            __syncwarp();
            const float4* src = g_llr4 + (size_t)s * SEG_STEPS * 4;
            float4* dst = ring + slot * SEG_STEPS * 4;
#pragma unroll
            for (int k = 0; k < (SEG_STEPS * 4) / 32; k++)
                dst[k * 32 + lane] = src[k * 32 + lane];
            __syncwarp();
            __threadfence_block();
            if (lane == 0) s_ready[slot] = s + 1;
        }
    } else if (tid == 0) {
        // ------------------ consumer (the chain) ------------------
        unsigned long long P01 = 0ull, P23 = 0ull, P45 = 0ull, P67 = 0ull;
        int t = 0;

        for (int s = 0; s < nSegs; s++) {
            int slot = s & (NSEG - 1);
            while (s_ready[slot] < s + 1) { /* spin */ }
            __threadfence_block();

            const ulonglong2* base =
                reinterpret_cast<const ulonglong2*>(ring + slot * SEG_STEPS * 4);
            int steps = min(SEG_STEPS, T - s * SEG_STEPS);

            int nblk = steps >> 4;          // full 16-step blocks
            for (int blk = 0; blk < nblk; blk++) {
                // checkpoint w before step t (t multiple of 16)
                {
                    float w0, w1, w2, w3, w4, w5, w6, w7;
                    f2_unpack(P01, w0, w1); f2_unpack(P23, w2, w3);
                    f2_unpack(P45, w4, w5); f2_unpack(P67, w6, w7);
                    float4* ck = g_ckpt + (size_t)(t >> 4) * 2;
                    ck[0] = make_float4(w0, w1, w2, w3);
                    ck[1] = make_float4(w4, w5, w6, w7);
                }
                const ulonglong2* bb = base + blk * 16 * 2;
#pragma unroll
                for (int j = 0; j < 16; j++) {
                    ulonglong2 v0 = bb[j * 2 + 0];   // (l0,l1),(l8,l9) | (l2,l3),(l10,l11)
                    ulonglong2 v1 = bb[j * 2 + 1];   // (l4,l5),(l12,l13) | (l6,l7),(l14,l15)
                    // careful: each ulonglong2 covers ONE float4 (16B)... no:
                    // ulonglong2 is 16B = one float4 = 2 pairs. 4 float4/step = 4 u2 loads? 
                    // base stride: 4 float4/step = 64B = 4 ulonglong2 per... 
                    // (see indexing fix below)
                    (void)v0; (void)v1;
                    break;
                }
                // --- correct indexing: 4 ulonglong2 per step (64B) ---
#pragma unroll
                for (int j = 0; j < 16; j++) {
                    const ulonglong2* sp = reinterpret_cast<const ulonglong2*>(
                        reinterpret_cast<const float4*>(base) + (blk * 16 + j) * 4);
                    ulonglong2 u0 = sp[0];   // (l0,l1),(l8,l9)
                    ulonglong2 u1 = sp[1];   // (l2,l3),(l10,l11)
                    ulonglong2 u2 = sp[2];   // (l4,l5),(l12,l13)
                    ulonglong2 u3 = sp[3];   // (l6,l7),(l14,l15)
                    acs_step(P01, P23, P45, P67,
                             u0.x, u0.y, u1.x, u1.y, u2.x, u2.y, u3.x, u3.y);
                }
                t += 16;
            }
            // tail (< 16 steps); T=250000 is a multiple of 16 so in practice
            // this only handles a checkpoint-aligned remainder.
            int rem = steps - (nblk << 4);
            if (rem > 0) {
                if ((t & 15) == 0) {
                    float w0, w1, w2, w3, w4, w5, w6, w7;
                    f2_unpack(P01, w0, w1); f2_unpack(P23, w2, w3);
                    f2_unpack(P45, w4, w5); f2_unpack(P67, w6, w7);
                    float4* ck = g_ckpt + (size_t)(t >> 4) * 2;
                    ck[0] = make_float4(w0, w1, w2, w3);
                    ck[1] = make_float4(w4, w5, w6, w7);
                }
                for (int j = 0; j < rem; j++) {
                    const ulonglong2* sp = reinterpret_cast<const ulonglong2*>(
                        reinterpret_cast<const float4*>(base) + ((nblk << 4) + j) * 4);
                    ulonglong2 u0 = sp[0];
                    ulonglong2 u1 = sp[1];
                    ulonglong2 u2 = sp[2];
                    ulonglong2 u3 = sp[3];
                    acs_step(P01, P23, P45, P67,
                             u0.x, u0.y, u1.x, u1.y, u2.x, u2.y, u3.x, u3.y);
                }
                t += rem;
            }
            __threadfence_block();
            s_freed[slot] = s + 1;
        }
    }
}

// ============================================================================
// K3: replay each 16-step chunk from its checkpoint, emit detected bits.
// Bit-exact: scalar __fadd_rn / fminf == lanewise add.rn.f32x2 / min.f32.
// ============================================================================
__global__ __launch_bounds__(128)
void k3_bits(float* __restrict__ out_bits, int T)
{
    int c = blockIdx.x * blockDim.x + threadIdx.x;
    int t0 = c * CKPT_STRIDE;
    if (t0 >= T) return;

    float4 c0 = g_ckpt[(size_t)c * 2 + 0];
    float4 c1 = g_ckpt[(size_t)c * 2 + 1];
    float w0 = c0.x, w1 = c0.y, w2 = c0.z, w3 = c0.w;
    float w4 = c1.x, w5 = c1.y, w6 = c1.z, w7 = c1.w;

    int n = min(CKPT_STRIDE, T - t0);
    for (int j = 0; j < n; j++) {
        float best = w0; int bi = 0;
        if (w1 < best) { best = w1; bi = 1; }
        if (w2 < best) { best = w2; bi = 2; }
        if (w3 < best) { best = w3; bi = 3; }
        if (w4 < best) { best = w4; bi = 4; }
        if (w5 < best) { best = w5; bi = 5; }
        if (w6 < best) { best = w6; bi = 6; }
        if (w7 < best) { best = w7; bi = 7; }
        out_bits[t0 + j] = (float)(bi & 1);

        const float4* q = g_llr4 + (size_t)(t0 + j) * 4;
        float4 q0 = q[0], q1 = q[1], q2 = q[2], q3 = q[3];
        float nw0 = fminf(__fadd_rn(w0, q0.x), __fadd_rn(w1, q0.y));
        float nw4 = fminf(__fadd_rn(w0, q0.z), __fadd_rn(w1, q0.w));
        float nw1 = fminf(__fadd_rn(w2, q1.x), __fadd_rn(w3, q1.y));
        float nw5 = fminf(__fadd_rn(w2, q1.z), __fadd_rn(w3, q1.w));
        float nw2 = fminf(__fadd_rn(w4, q2.x), __fadd_rn(w5, q2.y));
        float nw6 = fminf(__fadd_rn(w4, q2.z), __fadd_rn(w5, q2.w));
        float nw3 = fminf(__fadd_rn(w6, q3.x), __fadd_rn(w7, q3.y));
        float nw7 = fminf(__fadd_rn(w6, q3.z), __fadd_rn(w7, q3.w));
        w0 = nw0; w1 = nw1; w2 = nw2; w3 = nw3;
        w4 = nw4; w5 = nw5; w6 = nw6; w7 = nw7;
    }
}

// ============================================================================
extern "C" void kernel_launch(void* const* d_in, const int* in_sizes, int n_in,
                              void* d_out, int out_size)
{
    const float* rx = (const float*)d_in[0];
    const float* W1 = (const float*)d_in[1];
    const float* b1 = (const float*)d_in[2];
    const float* W2 = (const float*)d_in[3];
    const float* b2 = (const float*)d_in[4];
    int T = in_sizes[0];

    float* out = (float*)d_out;
    int sections = (T > 0) ? (out_size / T) : 0;
    float* out_det = out;
    float* out_cb  = (sections >= 2) ? out + T     : out;
    float* out_cw  = (sections >= 3) ? out + 2 * T : out_cb;

    int grid1 = (T + 127) / 128;
    k1_llr<<<grid1, 128>>>(rx, W1, b1, W2, b2, out_cb, out_cw, T);

    k2_scan<<<1, 128>>>(T);

    int nChunks = (T + CKPT_STRIDE - 1) / CKPT_STRIDE;
    int grid3 = (nChunks + 127) / 128;
    k3_bits<<<grid3, 128>>>(out_det, T);
}